// round 3
// baseline (speedup 1.0000x reference)
#include <cuda_runtime.h>
#include <cstdint>

#define NN 100000
#define EE 800000
#define HH 64
#define QMM 32
#define BB 100
#define LL 4
#define EPS_BN 1e-5f

// ---------------- scratch (static __device__ — no allocations allowed) ----------------
__device__ float g_feat[(size_t)EE * 64];   // [z_re(32) | z_im(32)] per edge, 204.8 MB
__device__ int   g_eg[EE];                  // graph id per edge
__device__ float g_agg[(size_t)NN * 64];    // edge aggregation
__device__ float g_y1[(size_t)NN * 64];     // pre-BN1 activations
__device__ float g_y2[(size_t)NN * 64];     // pre-BN2 activations
__device__ float g_xb[(size_t)NN * 64];     // node feature ping buffer
__device__ float g_wtab[BB * QMM];          // per-graph eigen weights w[B,Q*M]
__device__ float g_Wc[128 * 64];            // fused edge weight [W1;W2]
__device__ float g_bc[64];                  // fused edge bias
__device__ float g_stats[256];              // [bn1 sum | bn1 sq | bn2 sum | bn2 sq]

// ---------------- f32x2 packed math helpers (Blackwell) ----------------
__device__ __forceinline__ unsigned long long pack2(float a, float b) {
    unsigned long long r;
    asm("mov.b64 %0, {%1, %2};" : "=l"(r) : "f"(a), "f"(b));
    return r;
}
__device__ __forceinline__ void ffma2(unsigned long long& d, unsigned long long a, unsigned long long b) {
    asm("fma.rn.f32x2 %0, %1, %2, %0;" : "+l"(d) : "l"(a), "l"(b));
}
__device__ __forceinline__ float2 unpack2(unsigned long long v) {
    float2 r;
    asm("mov.b64 {%0, %1}, %2;" : "=f"(r.x), "=f"(r.y) : "l"(v));
    return r;
}

// ---------------- one-time precompute ----------------

// z = pe[src] * conj(pe[dst]); one warp per edge, lane = (q,m)
__global__ __launch_bounds__(256) void z_kernel(const float* __restrict__ pe,
                                                const int* __restrict__ ei,
                                                const int* __restrict__ batch) {
    int e = blockIdx.x * 8 + (threadIdx.x >> 5);
    int qm = threadIdx.x & 31;
    int src = ei[e];
    int dst = ei[EE + e];
    const float2* pe2 = (const float2*)pe;
    float2 zs = pe2[(size_t)src * 32 + qm];
    float2 zd = pe2[(size_t)dst * 32 + qm];
    float zr = zs.x * zd.x + zs.y * zd.y;
    float zi = zs.y * zd.x - zs.x * zd.y;
    g_feat[(size_t)e * 64 + qm] = zr;
    g_feat[(size_t)e * 64 + 32 + qm] = zi;
    if (qm == 0) g_eg[e] = batch[src];
}

__global__ void copy_pe_kernel(const float* __restrict__ pe, float* __restrict__ out) {
    size_t i = (size_t)blockIdx.x * 256 + threadIdx.x;   // < N*16 float4
    ((float4*)out)[i] = ((const float4*)pe)[i];
}

// ---------------- per-layer small kernels ----------------

__global__ void zero_kernel() {
    size_t i = (size_t)blockIdx.x * 256 + threadIdx.x;   // < N*16 float4
    ((float4*)g_agg)[i] = make_float4(0.f, 0.f, 0.f, 0.f);
    if (blockIdx.x == 0) g_stats[threadIdx.x] = 0.f;
}

// eigenvalue MLP: w[b,qm] = phi(Lam[b,qm])
__global__ void phi_kernel(const float* __restrict__ Lam, const float* __restrict__ pw1,
                           const float* __restrict__ pb1, const float* __restrict__ pw2,
                           const float* __restrict__ pb2, int l) {
    int i = blockIdx.x * 256 + threadIdx.x;
    if (i >= BB * QMM) return;
    float lam = Lam[i];
    float s = pb2[l];
#pragma unroll
    for (int j = 0; j < 16; j++) {
        float h = fmaxf(lam * pw1[l * 16 + j] + pb1[l * 16 + j], 0.f);
        s += h * pw2[l * 16 + j];
    }
    g_wtab[i] = s;
}

// W1 = enc_w@lin_w ; W2 = lin_w ; bc = enc_b@lin_w + lin_b
__global__ void fuse_kernel(const float* __restrict__ enc_w, const float* __restrict__ enc_b,
                            const float* __restrict__ lin_w, const float* __restrict__ lin_b, int l) {
    int k = blockIdx.x;    // 0..63
    int h = threadIdx.x;   // 0..63
    const float* ew = enc_w + (size_t)l * 64 * 64;
    const float* lw = lin_w + (size_t)l * 64 * 64;
    float s = 0.f;
    for (int j = 0; j < 64; j++) s += ew[k * 64 + j] * lw[j * 64 + h];
    g_Wc[k * 64 + h] = s;
    g_Wc[(64 + k) * 64 + h] = lw[k * 64 + h];
    if (k == 0) {
        float b = lin_b[l * 64 + h];
        for (int j = 0; j < 64; j++) b += enc_b[l * 64 + j] * lw[j * 64 + h];
        g_bc[h] = b;
    }
}

// ---------------- edge kernel: [feat|ea] @ Wc (K=128), relu, scatter-add ----------------
__global__ __launch_bounds__(256) void edge_kernel(const float* __restrict__ edge_attr,
                                                   const float* __restrict__ xcur,
                                                   const int* __restrict__ ei) {
    __shared__ float sW[128 * 64];   // 32 KB
    __shared__ float sA[64 * 32];    // 8 KB, k-major
    __shared__ int sSrc[32], sDst[32], sG[32];
    __shared__ float sB[64];
    int t = threadIdx.x;
    int e0 = blockIdx.x * 32;
    {
        const float4* Wv = (const float4*)g_Wc;
        float4* sWv = (float4*)sW;
#pragma unroll
        for (int i = 0; i < 8; i++) sWv[t + 256 * i] = Wv[t + 256 * i];
    }
    if (t < 32) {
        sSrc[t] = ei[e0 + t];
        sDst[t] = ei[EE + e0 + t];
        sG[t] = g_eg[e0 + t];
    } else if (t < 96) {
        sB[t - 32] = g_bc[t - 32];
    }
    __syncthreads();

    int e_loc = t & 31, part = t >> 5;   // 32 edges x 8 k-chunks
    int e = e0 + e_loc;
    int k0 = part * 8;

    // phase-1 staging: feat * we (k = 0..63)
    {
        const float* wv = g_wtab + sG[e_loc] * QMM;
        float4 f0 = *(const float4*)(g_feat + (size_t)e * 64 + k0);
        float4 f1 = *(const float4*)(g_feat + (size_t)e * 64 + k0 + 4);
        int m0 = k0 & 31;
        sA[(k0 + 0) * 32 + e_loc] = f0.x * wv[m0 + 0];
        sA[(k0 + 1) * 32 + e_loc] = f0.y * wv[m0 + 1];
        sA[(k0 + 2) * 32 + e_loc] = f0.z * wv[m0 + 2];
        sA[(k0 + 3) * 32 + e_loc] = f0.w * wv[m0 + 3];
        sA[(k0 + 4) * 32 + e_loc] = f1.x * wv[m0 + 4];
        sA[(k0 + 5) * 32 + e_loc] = f1.y * wv[m0 + 5];
        sA[(k0 + 6) * 32 + e_loc] = f1.z * wv[m0 + 6];
        sA[(k0 + 7) * 32 + e_loc] = f1.w * wv[m0 + 7];
    }
    __syncthreads();

    int tx = t & 63, ty = t >> 6;   // channel, edge-octet
    unsigned long long acc[4] = {0ull, 0ull, 0ull, 0ull};
#pragma unroll 8
    for (int k = 0; k < 64; k++) {
        float w = sW[k * 64 + tx];
        unsigned long long w2 = pack2(w, w);
        const ulonglong2* ap = (const ulonglong2*)(sA + k * 32 + ty * 8);
        ulonglong2 a01 = ap[0];
        ulonglong2 a23 = ap[1];
        ffma2(acc[0], a01.x, w2);
        ffma2(acc[1], a01.y, w2);
        ffma2(acc[2], a23.x, w2);
        ffma2(acc[3], a23.y, w2);
    }
    __syncthreads();

    // phase-2 staging: edge_attr (k = 64..127)
    {
        float4 f0 = *(const float4*)(edge_attr + (size_t)e * 64 + k0);
        float4 f1 = *(const float4*)(edge_attr + (size_t)e * 64 + k0 + 4);
        sA[(k0 + 0) * 32 + e_loc] = f0.x;
        sA[(k0 + 1) * 32 + e_loc] = f0.y;
        sA[(k0 + 2) * 32 + e_loc] = f0.z;
        sA[(k0 + 3) * 32 + e_loc] = f0.w;
        sA[(k0 + 4) * 32 + e_loc] = f1.x;
        sA[(k0 + 5) * 32 + e_loc] = f1.y;
        sA[(k0 + 6) * 32 + e_loc] = f1.z;
        sA[(k0 + 7) * 32 + e_loc] = f1.w;
    }
    __syncthreads();
#pragma unroll 8
    for (int k = 0; k < 64; k++) {
        float w = sW[(64 + k) * 64 + tx];
        unsigned long long w2 = pack2(w, w);
        const ulonglong2* ap = (const ulonglong2*)(sA + k * 32 + ty * 8);
        ulonglong2 a01 = ap[0];
        ulonglong2 a23 = ap[1];
        ffma2(acc[0], a01.x, w2);
        ffma2(acc[1], a01.y, w2);
        ffma2(acc[2], a23.x, w2);
        ffma2(acc[3], a23.y, w2);
    }

    float b = sB[tx];
#pragma unroll
    for (int p = 0; p < 4; p++) {
        float2 v = unpack2(acc[p]);
        int ea = ty * 8 + p * 2;
        float vA = v.x + b + xcur[(size_t)sSrc[ea] * 64 + tx];
        float vB = v.y + b + xcur[(size_t)sSrc[ea + 1] * 64 + tx];
        vA = fmaxf(vA, 0.f);
        vB = fmaxf(vB, 0.f);
        atomicAdd(&g_agg[(size_t)sDst[ea] * 64 + tx], vA);
        atomicAdd(&g_agg[(size_t)sDst[ea + 1] * 64 + tx], vB);
    }
}

// ---------------- node kernels ----------------

// y1 = (x + agg) @ mlp_w1 + b1 ; accumulate BN1 column stats
__global__ __launch_bounds__(256) void nodeA_kernel(const float* __restrict__ xcur,
                                                    const float* __restrict__ W,
                                                    const float* __restrict__ bias, int l) {
    __shared__ float sW[64 * 64];
    __shared__ float sA[64 * 32];
    __shared__ float sRs[256], sRq[256];
    int t = threadIdx.x;
    int n0 = blockIdx.x * 32;
    {
        const float4* Wv = (const float4*)(W + (size_t)l * 4096);
        float4* sWv = (float4*)sW;
#pragma unroll
        for (int i = 0; i < 4; i++) sWv[t + 256 * i] = Wv[t + 256 * i];
    }
    int n_loc = t & 31, part = t >> 5;
    int k0 = part * 8;
    {
        size_t base = (size_t)(n0 + n_loc) * 64 + k0;
        float4 x0 = *(const float4*)(xcur + base);
        float4 x1 = *(const float4*)(xcur + base + 4);
        float4 a0 = *(const float4*)(g_agg + base);
        float4 a1 = *(const float4*)(g_agg + base + 4);
        sA[(k0 + 0) * 32 + n_loc] = x0.x + a0.x;
        sA[(k0 + 1) * 32 + n_loc] = x0.y + a0.y;
        sA[(k0 + 2) * 32 + n_loc] = x0.z + a0.z;
        sA[(k0 + 3) * 32 + n_loc] = x0.w + a0.w;
        sA[(k0 + 4) * 32 + n_loc] = x1.x + a1.x;
        sA[(k0 + 5) * 32 + n_loc] = x1.y + a1.y;
        sA[(k0 + 6) * 32 + n_loc] = x1.z + a1.z;
        sA[(k0 + 7) * 32 + n_loc] = x1.w + a1.w;
    }
    __syncthreads();

    int tx = t & 63, ty = t >> 6;
    unsigned long long acc[4] = {0ull, 0ull, 0ull, 0ull};
#pragma unroll 8
    for (int k = 0; k < 64; k++) {
        float w = sW[k * 64 + tx];
        unsigned long long w2 = pack2(w, w);
        const ulonglong2* ap = (const ulonglong2*)(sA + k * 32 + ty * 8);
        ulonglong2 a01 = ap[0];
        ulonglong2 a23 = ap[1];
        ffma2(acc[0], a01.x, w2);
        ffma2(acc[1], a01.y, w2);
        ffma2(acc[2], a23.x, w2);
        ffma2(acc[3], a23.y, w2);
    }
    float bb = bias[l * 64 + tx];
    float s = 0.f, q = 0.f;
#pragma unroll
    for (int p = 0; p < 4; p++) {
        float2 v = unpack2(acc[p]);
        int na = ty * 8 + p * 2;
        float yA = v.x + bb, yB = v.y + bb;
        g_y1[(size_t)(n0 + na) * 64 + tx] = yA;
        g_y1[(size_t)(n0 + na + 1) * 64 + tx] = yB;
        s += yA + yB;
        q += yA * yA + yB * yB;
    }
    sRs[t] = s;
    sRq[t] = q;
    __syncthreads();
    if (t < 64) {
        s = sRs[t] + sRs[64 + t] + sRs[128 + t] + sRs[192 + t];
        q = sRq[t] + sRq[64 + t] + sRq[128 + t] + sRq[192 + t];
        atomicAdd(&g_stats[t], s);
        atomicAdd(&g_stats[64 + t], q);
    }
}

// y2 = relu(BN1(y1)) @ mlp_w2 + b2 ; accumulate BN2 column stats
__global__ __launch_bounds__(256) void nodeB_kernel(const float* __restrict__ W,
                                                    const float* __restrict__ bias,
                                                    const float* __restrict__ bg,
                                                    const float* __restrict__ bnb, int l) {
    __shared__ float sW[64 * 64];
    __shared__ float sA[64 * 32];
    __shared__ float sSc[64], sSh[64];
    __shared__ float sRs[256], sRq[256];
    int t = threadIdx.x;
    int n0 = blockIdx.x * 32;
    {
        const float4* Wv = (const float4*)(W + (size_t)l * 4096);
        float4* sWv = (float4*)sW;
#pragma unroll
        for (int i = 0; i < 4; i++) sWv[t + 256 * i] = Wv[t + 256 * i];
    }
    if (t < 64) {
        float mu = g_stats[t] * (1.0f / NN);
        float var = g_stats[64 + t] * (1.0f / NN) - mu * mu;
        float rs = rsqrtf(var + EPS_BN);
        float sc = rs * bg[l * 64 + t];
        sSc[t] = sc;
        sSh[t] = bnb[l * 64 + t] - mu * sc;
    }
    __syncthreads();
    int n_loc = t & 31, part = t >> 5;
    int k0 = part * 8;
    {
        size_t base = (size_t)(n0 + n_loc) * 64 + k0;
        float4 y0 = *(const float4*)(g_y1 + base);
        float4 y1v = *(const float4*)(g_y1 + base + 4);
        sA[(k0 + 0) * 32 + n_loc] = fmaxf(y0.x * sSc[k0 + 0] + sSh[k0 + 0], 0.f);
        sA[(k0 + 1) * 32 + n_loc] = fmaxf(y0.y * sSc[k0 + 1] + sSh[k0 + 1], 0.f);
        sA[(k0 + 2) * 32 + n_loc] = fmaxf(y0.z * sSc[k0 + 2] + sSh[k0 + 2], 0.f);
        sA[(k0 + 3) * 32 + n_loc] = fmaxf(y0.w * sSc[k0 + 3] + sSh[k0 + 3], 0.f);
        sA[(k0 + 4) * 32 + n_loc] = fmaxf(y1v.x * sSc[k0 + 4] + sSh[k0 + 4], 0.f);
        sA[(k0 + 5) * 32 + n_loc] = fmaxf(y1v.y * sSc[k0 + 5] + sSh[k0 + 5], 0.f);
        sA[(k0 + 6) * 32 + n_loc] = fmaxf(y1v.z * sSc[k0 + 6] + sSh[k0 + 6], 0.f);
        sA[(k0 + 7) * 32 + n_loc] = fmaxf(y1v.w * sSc[k0 + 7] + sSh[k0 + 7], 0.f);
    }
    __syncthreads();

    int tx = t & 63, ty = t >> 6;
    unsigned long long acc[4] = {0ull, 0ull, 0ull, 0ull};
#pragma unroll 8
    for (int k = 0; k < 64; k++) {
        float w = sW[k * 64 + tx];
        unsigned long long w2 = pack2(w, w);
        const ulonglong2* ap = (const ulonglong2*)(sA + k * 32 + ty * 8);
        ulonglong2 a01 = ap[0];
        ulonglong2 a23 = ap[1];
        ffma2(acc[0], a01.x, w2);
        ffma2(acc[1], a01.y, w2);
        ffma2(acc[2], a23.x, w2);
        ffma2(acc[3], a23.y, w2);
    }
    float bb = bias[l * 64 + tx];
    float s = 0.f, q = 0.f;
#pragma unroll
    for (int p = 0; p < 4; p++) {
        float2 v = unpack2(acc[p]);
        int na = ty * 8 + p * 2;
        float yA = v.x + bb, yB = v.y + bb;
        g_y2[(size_t)(n0 + na) * 64 + tx] = yA;
        g_y2[(size_t)(n0 + na + 1) * 64 + tx] = yB;
        s += yA + yB;
        q += yA * yA + yB * yB;
    }
    sRs[t] = s;
    sRq[t] = q;
    __syncthreads();
    if (t < 64) {
        s = sRs[t] + sRs[64 + t] + sRs[128 + t] + sRs[192 + t];
        q = sRq[t] + sRq[64 + t] + sRq[128 + t] + sRq[192 + t];
        atomicAdd(&g_stats[128 + t], s);
        atomicAdd(&g_stats[192 + t], q);
    }
}

// x_out = BN2(y2) [+ relu unless last layer]
__global__ void bn_apply_kernel(const float* __restrict__ bg, const float* __restrict__ bnb,
                                float* __restrict__ xout, int l, int do_relu) {
    int i = blockIdx.x * 256 + threadIdx.x;   // < N*64
    int h = i & 63;
    float mu = g_stats[128 + h] * (1.0f / NN);
    float var = g_stats[192 + h] * (1.0f / NN) - mu * mu;
    float rs = rsqrtf(var + EPS_BN);
    float sc = rs * bg[l * 64 + h];
    float sh = bnb[l * 64 + h] - mu * sc;
    float v = g_y2[i] * sc + sh;
    if (do_relu) v = fmaxf(v, 0.f);
    xout[i] = v;
}

// ---------------- launcher ----------------
extern "C" void kernel_launch(void* const* d_in, const int* in_sizes, int n_in,
                              void* d_out, int out_size) {
    const float* x        = (const float*)d_in[0];
    const float* pe       = (const float*)d_in[1];
    const float* Lam      = (const float*)d_in[2];
    const float* edge_attr= (const float*)d_in[3];
    const float* pw1      = (const float*)d_in[4];
    const float* pb1      = (const float*)d_in[5];
    const float* pw2      = (const float*)d_in[6];
    const float* pb2      = (const float*)d_in[7];
    const float* enc_w    = (const float*)d_in[8];
    const float* enc_b    = (const float*)d_in[9];
    const float* lin_w    = (const float*)d_in[10];
    const float* lin_b    = (const float*)d_in[11];
    const float* mw1      = (const float*)d_in[12];
    const float* mb1      = (const float*)d_in[13];
    const float* bn1g     = (const float*)d_in[14];
    const float* bn1b     = (const float*)d_in[15];
    const float* mw2      = (const float*)d_in[16];
    const float* mb2      = (const float*)d_in[17];
    const float* bn2g     = (const float*)d_in[18];
    const float* bn2b     = (const float*)d_in[19];
    const int*   ei       = (const int*)d_in[20];
    const int*   batch    = (const int*)d_in[21];
    float* out = (float*)d_out;

    float* xb = nullptr;
    cudaGetSymbolAddress((void**)&xb, g_xb);

    // pe passthrough into second half of the output
    if (out_size >= (int)(2u * NN * 64)) {
        copy_pe_kernel<<<NN * 16 / 256, 256>>>(pe, out + (size_t)NN * 64);
    }
    // layer-invariant complex edge features + edge graph ids
    z_kernel<<<EE / 8, 256>>>(pe, ei, batch);

    for (int l = 0; l < LL; l++) {
        const float* xcur = (l == 0) ? x : (const float*)xb;
        float* xout = (l == LL - 1) ? out : xb;
        zero_kernel<<<NN * 16 / 256, 256>>>();
        phi_kernel<<<(BB * QMM + 255) / 256, 256>>>(Lam, pw1, pb1, pw2, pb2, l);
        fuse_kernel<<<64, 64>>>(enc_w, enc_b, lin_w, lin_b, l);
        edge_kernel<<<EE / 32, 256>>>(edge_attr, xcur, ei);
        nodeA_kernel<<<NN / 32, 256>>>(xcur, mw1, mb1, l);
        nodeB_kernel<<<NN / 32, 256>>>(mw2, mb2, bn1g, bn1b, l);
        bn_apply_kernel<<<NN * 64 / 256, 256>>>(bn2g, bn2b, xout, l, (l != LL - 1) ? 1 : 0);
    }
}